// round 14
// baseline (speedup 1.0000x reference)
#include <cuda_runtime.h>
#include <stdint.h>

#define VOCAB 512
#define WCHARS 24
#define WPB 8          // warps per block (scatter)

// Node 1: pure zero-fill kernel. No dependency chains — back-to-back
// independent STG.128 at full issue rate, and (unlike engine memset) it
// leaves the output lines RESIDENT-DIRTY in L2 for node 2.
__global__ void __launch_bounds__(256)
fofe_fill_kernel(float4* __restrict__ out4, long long n4)
{
    const float4 z = make_float4(0.f, 0.f, 0.f, 0.f);
    long long i = (long long)blockIdx.x * blockDim.x + threadIdx.x;
    const long long stride = (long long)gridDim.x * blockDim.x;
    for (; i < n4; i += stride)
        out4[i] = z;
}

// Node 2: lean scatter. Warp per row; <=24 weighted chars; duplicates within
// a row are summed across the (tiny) equal-char group via __match_any_sync,
// group leader issues ONE plain STG.32 into the L2-resident zeroed line.
// Tail (lengths) fused. int64 inputs arrive as int32 (jax x64 disabled).
__global__ void __launch_bounds__(WPB * 32)
fofe_scatter_kernel(const int* __restrict__ sents,
                    const int* __restrict__ lengths,
                    const float* __restrict__ alpha_p,
                    float* __restrict__ out,
                    int nrows,
                    long long main_elems,
                    int extra,
                    int nlen)
{
    const int warp = threadIdx.x >> 5;
    const int lane = threadIdx.x & 31;
    const int row  = blockIdx.x * WPB + warp;

    // tail: (out, lengths) second output appended to d_out (overwrites zeros)
    if (blockIdx.x == 0 && (int)threadIdx.x < extra) {
        int i = threadIdx.x;
        out[main_elems + i] = (i < nlen) ? (float)lengths[i] : 0.0f;
    }
    if (row >= nrows) return;

    int c = 0;
    if (lane < WCHARS)
        c = sents[(long long)row * WCHARS + lane];
    const float a = __ldg(alpha_p);

    const bool valid = (lane < WCHARS) && (c > 0) && (c < VOCAB);
    const unsigned nz = __ballot_sync(0xffffffffu, valid);

    if (valid) {
        // weight: alpha^(# nonzero chars strictly after this position)
        const int suffix = __popc(nz & (0xfffffffeu << lane));
        const float w = (suffix == 0) ? 1.0f
                                      : exp2f(log2f(a) * (float)suffix);

        // lanes holding the same char: sum weights across the group
        // (group mask is uniform within the group; loop is ~1 iteration)
        const unsigned grp = __match_any_sync(nz, c);
        float wsum = 0.0f;
        unsigned m = grp;
        while (m) {
            const int j = __ffs(m) - 1;
            m &= m - 1;
            wsum += __shfl_sync(grp, w, j);
        }

        if (lane == (__ffs(grp) - 1))                 // group leader
            out[(long long)row * VOCAB + c] = wsum;   // plain store, L2 hit
    }
}

extern "C" void kernel_launch(void* const* d_in, const int* in_sizes, int n_in,
                              void* d_out, int out_size)
{
    const int*   sents   = (const int*)d_in[0];
    const int*   lengths = (const int*)d_in[1];
    const float* alpha   = (const float*)d_in[2];
    float*       out     = (float*)d_out;

    const int nrows = in_sizes[0] / WCHARS;             // B*S = 32768
    const long long main_elems = (long long)nrows * VOCAB;
    const int nlen = in_sizes[1];

    long long extra_ll = (long long)out_size - main_elems;
    if (extra_ll < 0) extra_ll = 0;
    if (extra_ll > WPB * 32) extra_ll = WPB * 32;

    // node 1: zero-fill (out_size for this problem is divisible by 4;
    // guard the remainder anyway via the scatter-side tail overwrite)
    const long long n4 = (long long)out_size / 4;
    fofe_fill_kernel<<<2048, 256>>>(reinterpret_cast<float4*>(out), n4);

    // node 2: sparse exact-value scatter + tail
    const int blocks = (nrows + WPB - 1) / WPB;
    fofe_scatter_kernel<<<blocks, WPB * 32>>>(sents, lengths, alpha, out,
                                              nrows, main_elems,
                                              (int)extra_ll, nlen);
}

// round 15
// speedup vs baseline: 1.2653x; 1.2653x over previous
#include <cuda_runtime.h>
#include <stdint.h>

#define VOCAB 512
#define WCHARS 24
#define WPB 8          // warps per block

// Fused single pass, one warp per (b,s) row. Atomic-free sparse histogram:
//   - equal chars deduped with __match_any_sync; group leader shfl-sums the
//     group's weights and writes ONE plain STS.32 (no ATOMS latency)
//   - dirty 16B-chunk mask built in registers with __reduce_or_sync
//     (no smem atomicOr / readback)
//   - only dirty chunks are zeroed and read back (predicated LDS.128);
//     clean chunks stream register zeros via __stcs
// Tail output (lengths) fused into block 0. int64 inputs arrive as int32
// (jax x64 disabled).
__global__ void __launch_bounds__(WPB * 32)
fofe_kernel(const int* __restrict__ sents,
            const int* __restrict__ lengths,
            const float* __restrict__ alpha_p,
            float* __restrict__ out,
            int nrows,
            long long main_elems,
            int extra,
            int nlen)
{
    __shared__ __align__(128) float hist[WPB][VOCAB];   // 16 KB

    const int warp = threadIdx.x >> 5;
    const int lane = threadIdx.x & 31;
    const int row  = blockIdx.x * WPB + warp;

    // fused tail: (out, lengths) second output appended to d_out
    if (blockIdx.x == 0 && (int)threadIdx.x < extra) {
        int i = threadIdx.x;
        out[main_elems + i] = (i < nlen) ? (float)lengths[i] : 0.0f;
    }
    if (row >= nrows) return;

    float* h = hist[warp];

    int c = 0;
    if (lane < WCHARS)
        c = sents[(long long)row * WCHARS + lane];
    const float a = __ldg(alpha_p);

    const bool valid = (lane < WCHARS) && (c > 0) && (c < VOCAB);
    const unsigned nz = __ballot_sync(0xffffffffu, valid);

    // dirty 16B-chunk mask (128 chunks -> 4 words), all in registers
    const int chunk = c >> 2;
    unsigned dw[4];
    #pragma unroll
    for (int j = 0; j < 4; ++j) {
        const unsigned mine =
            (valid && (chunk >> 5) == j) ? (1u << (chunk & 31)) : 0u;
        dw[j] = __reduce_or_sync(0xffffffffu, mine);
    }

    // zero my dirty chunk (duplicate zeroing across lanes is harmless)
    if (valid)
        *reinterpret_cast<float4*>(&h[c & ~3]) =
            make_float4(0.f, 0.f, 0.f, 0.f);
    __syncwarp();                       // zeros ordered before value stores

    if (valid) {
        // weight: alpha^(# nonzero chars strictly after this position)
        const int suffix = __popc(nz & (0xfffffffeu << lane));
        const float w = (suffix == 0) ? 1.0f
                                      : exp2f(log2f(a) * (float)suffix);

        // dedup equal chars: leader sums the group's weights (usually 1 iter)
        const unsigned grp = __match_any_sync(nz, c);
        float wsum = 0.0f;
        unsigned m = grp;
        while (m) {
            const int j = __ffs(m) - 1;
            m &= m - 1;
            wsum += __shfl_sync(grp, w, j);
        }
        if (lane == (__ffs(grp) - 1))
            h[c] = wsum;                // plain STS.32, no atomics
    }
    __syncwarp();

    // drain: predicated LDS.128 for dirty chunks, register zeros otherwise
    float4* o4 = reinterpret_cast<float4*>(out + (long long)row * VOCAB);
    #pragma unroll
    for (int j = 0; j < 4; ++j) {
        const int i = j * 32 + lane;
        const unsigned bit = (dw[j] >> lane) & 1u;
        float4 v = make_float4(0.f, 0.f, 0.f, 0.f);
        const unsigned saddr =
            (unsigned)__cvta_generic_to_shared(&h[i * 4]);
        asm volatile(
            "{ .reg .pred p; setp.ne.u32 p, %4, 0;\n"
            "  @p ld.shared.v4.f32 {%0,%1,%2,%3}, [%5]; }"
            : "+f"(v.x), "+f"(v.y), "+f"(v.z), "+f"(v.w)
            : "r"(bit), "r"(saddr));
        __stcs(&o4[i], v);              // evict-first, never re-read
    }
}

extern "C" void kernel_launch(void* const* d_in, const int* in_sizes, int n_in,
                              void* d_out, int out_size)
{
    const int*   sents   = (const int*)d_in[0];
    const int*   lengths = (const int*)d_in[1];
    const float* alpha   = (const float*)d_in[2];
    float*       out     = (float*)d_out;

    const int nrows = in_sizes[0] / WCHARS;             // B*S = 32768
    const long long main_elems = (long long)nrows * VOCAB;
    const int nlen = in_sizes[1];

    long long extra_ll = (long long)out_size - main_elems;
    if (extra_ll < 0) extra_ll = 0;
    if (extra_ll > WPB * 32) extra_ll = WPB * 32;

    const int blocks = (nrows + WPB - 1) / WPB;
    fofe_kernel<<<blocks, WPB * 32>>>(sents, lengths, alpha, out,
                                      nrows, main_elems, (int)extra_ll, nlen);
}

// round 17
// speedup vs baseline: 1.9342x; 1.5287x over previous
#include <cuda_runtime.h>
#include <stdint.h>

#define VOCAB 512
#define WCHARS 24
#define WPB 8          // warps per block

// One warp per (b,s) row. Sparse smem histogram: only the <=24 dirty 16B
// chunks are zeroed and read back; clean chunks stream register zeros.
// Dirty mask via smem atomicOr + readback (bit position = chunk&31 — a
// ballot CANNOT express this mapping; R16's attempt scrambled it).
// Drain uses DEFAULT-policy STG.128 so the 67MB output stays resident-dirty
// in L2 across back-to-back graph replays (vs __stcs evict-first).
// Tail output (lengths) fused into block 0. int64 inputs arrive as int32
// (jax x64 disabled).
__global__ void __launch_bounds__(WPB * 32)
fofe_kernel(const int* __restrict__ sents,
            const int* __restrict__ lengths,
            const float* __restrict__ alpha_p,
            float* __restrict__ out,
            int nrows,
            long long main_elems,
            int extra,
            int nlen)
{
    __shared__ float    hist[WPB][VOCAB];
    __shared__ unsigned dirty[WPB][4];      // 128 chunk bits per warp

    const int warp = threadIdx.x >> 5;
    const int lane = threadIdx.x & 31;
    const int row  = blockIdx.x * WPB + warp;

    // fused tail: (out, lengths) second output appended to d_out
    if (blockIdx.x == 0 && (int)threadIdx.x < extra) {
        int i = threadIdx.x;
        out[main_elems + i] = (i < nlen) ? (float)lengths[i] : 0.0f;
    }
    if (row >= nrows) return;

    float*    h  = hist[warp];
    unsigned* dm = dirty[warp];

    if (lane < 4) dm[lane] = 0u;

    int c = 0;
    if (lane < WCHARS)
        c = sents[(long long)row * WCHARS + lane];

    const bool valid = (lane < WCHARS) && (c > 0) && (c < VOCAB);
    const unsigned nz = __ballot_sync(0xffffffffu, valid);
    __syncwarp();                       // dm zeroing visible

    // mark + zero only the dirty 16B chunk holding this char's bin
    if (valid) {
        const int chunk = c >> 2;
        atomicOr(&dm[chunk >> 5], 1u << (chunk & 31));
        *reinterpret_cast<float4*>(&h[c & ~3]) =
            make_float4(0.f, 0.f, 0.f, 0.f);   // racing dup zeros are fine
    }
    __syncwarp();                       // zeros ordered before adds

    if (valid) {
        const int suffix = __popc(nz & (0xfffffffeu << lane));
        const float a = __ldg(alpha_p);
        const float w = (suffix == 0) ? 1.0f
                                      : exp2f(log2f(a) * (float)suffix);
        atomicAdd(&h[c], w);            // shared atomic, <=24 per row
    }
    __syncwarp();

    // broadcast-read the dirty mask once (1 LDS.128)
    const uint4 d = *reinterpret_cast<const uint4*>(dm);
    const unsigned dw[4] = { d.x, d.y, d.z, d.w };

    float4* o4 = reinterpret_cast<float4*>(out + (long long)row * VOCAB);
    #pragma unroll
    for (int j = 0; j < 4; ++j) {
        const int i = j * 32 + lane;            // chunk id: word j, bit lane
        const unsigned bit = (dw[j] >> lane) & 1u;
        float4 v = make_float4(0.f, 0.f, 0.f, 0.f);
        const unsigned saddr =
            (unsigned)__cvta_generic_to_shared(&h[i * 4]);
        // predicated LDS.128: no wavefronts for clean chunks, no branch
        asm volatile(
            "{ .reg .pred p; setp.ne.u32 p, %4, 0;\n"
            "  @p ld.shared.v4.f32 {%0,%1,%2,%3}, [%5]; }"
            : "+f"(v.x), "+f"(v.y), "+f"(v.z), "+f"(v.w)
            : "r"(bit), "r"(saddr));
        o4[i] = v;                              // default-policy STG.128
    }
}

extern "C" void kernel_launch(void* const* d_in, const int* in_sizes, int n_in,
                              void* d_out, int out_size)
{
    const int*   sents   = (const int*)d_in[0];
    const int*   lengths = (const int*)d_in[1];
    const float* alpha   = (const float*)d_in[2];
    float*       out     = (float*)d_out;

    const int nrows = in_sizes[0] / WCHARS;             // B*S = 32768
    const long long main_elems = (long long)nrows * VOCAB;
    const int nlen = in_sizes[1];

    long long extra_ll = (long long)out_size - main_elems;
    if (extra_ll < 0) extra_ll = 0;
    if (extra_ll > WPB * 32) extra_ll = WPB * 32;

    const int blocks = (nrows + WPB - 1) / WPB;
    fofe_kernel<<<blocks, WPB * 32>>>(sents, lengths, alpha, out,
                                      nrows, main_elems, (int)extra_ll, nlen);
}